// round 10
// baseline (speedup 1.0000x reference)
#include <cuda_runtime.h>
#include <cuda_fp16.h>
#include <cstdint>

// OctreeConvBnRelu via warp-level mma.sync (HMMA fp16, f32 accum).
// Round 10: M=256 tile, 2-D warp grid (4m x 2n) to amortize B-fragment reads,
// neigh pre-transposed to [27][N], 4-stage cp.async pipeline.

#define DEVFN __device__ __forceinline__

DEVFN uint32_t smem_u32(const void* p) {
    uint32_t a;
    asm("{ .reg .u64 t; cvta.to.shared.u64 t, %1; cvt.u32.u64 %0, t; }" : "=r"(a) : "l"(p));
    return a;
}
DEVFN uint32_t pack_h2(float x, float y) {
    __half2 v = __halves2half2(__float2half_rn(x), __float2half_rn(y));  // x = low
    return *(uint32_t*)&v;
}
DEVFN void ldmatrix_x4(uint32_t* r, uint32_t addr) {
    asm volatile("ldmatrix.sync.aligned.m8n8.x4.shared.b16 {%0,%1,%2,%3}, [%4];"
                 : "=r"(r[0]), "=r"(r[1]), "=r"(r[2]), "=r"(r[3]) : "r"(addr));
}
DEVFN void mma_f16(float* d, const uint32_t* a, uint32_t b0, uint32_t b1) {
    asm volatile(
        "mma.sync.aligned.m16n8k16.row.col.f32.f16.f16.f32 "
        "{%0,%1,%2,%3}, {%4,%5,%6,%7}, {%8,%9}, {%0,%1,%2,%3};"
        : "+f"(d[0]), "+f"(d[1]), "+f"(d[2]), "+f"(d[3])
        : "r"(a[0]), "r"(a[1]), "r"(a[2]), "r"(a[3]), "r"(b0), "r"(b1));
}
DEVFN void cp_async16(uint32_t smem_dst, const void* gsrc) {
    asm volatile("cp.async.cg.shared.global [%0], [%1], 16;"
                 :: "r"(smem_dst), "l"(gsrc) : "memory");
}
#define CP_COMMIT() asm volatile("cp.async.commit_group;" ::: "memory")
#define CP_WAIT3()  asm volatile("cp.async.wait_group 3;" ::: "memory")

// ------------------------- globals -------------------------
__device__ float g_sum[64];
__device__ float g_sumsq[64];
__device__ __align__(16) float g_scale[64];
__device__ __align__(16) float g_shift[64];
// B fragments: [27][ntile 8][lane 32] uint4 = {ks0.x, ks0.y, ks1.x, ks1.y} (4KB/k)
__device__ __align__(16) uint4 g_Bfrag4[27 * 256];
// fp16 data image: row = 32 half = 64B
static const int ROW_CAP = 301056;
__device__ __align__(16) uint8_t g_dataF16[(size_t)ROW_CAP * 64];
__device__ __align__(16) uint8_t g_zero_row[64];   // stays zero
// transposed neighbor table: [27][ROW_CAP]
__device__ int g_neighT[27 * ROW_CAP];

// ------------------------- data prep: f32 row -> fp16 row -------------------------
__global__ __launch_bounds__(256) void prep_data_kernel(const float* __restrict__ data, int N) {
    int r = blockIdx.x * 256 + threadIdx.x;
    if (r >= N || r >= ROW_CAP) return;
    const float4* src = (const float4*)(data + (size_t)r * 32);
    uint32_t u[16];
    #pragma unroll
    for (int i = 0; i < 8; i++) {
        float4 v = src[i];
        u[2 * i]     = pack_h2(v.x, v.y);
        u[2 * i + 1] = pack_h2(v.z, v.w);
    }
    uint4* dst = (uint4*)(g_dataF16 + (size_t)r * 64);
    #pragma unroll
    for (int i = 0; i < 4; i++)
        dst[i] = make_uint4(u[4 * i], u[4 * i + 1], u[4 * i + 2], u[4 * i + 3]);
}

// ------------------------- neigh transpose: [N,27] -> [27][N] -------------------------
__global__ __launch_bounds__(256) void prep_neigh_kernel(const int* __restrict__ neigh, int N) {
    __shared__ int s[256 * 27];
    int n0 = blockIdx.x * 256;
    int tid = threadIdx.x;
    int cnt = N - n0;
    if (cnt > 256) cnt = 256;
    for (int e = tid; e < cnt * 27; e += 256) s[e] = neigh[(size_t)n0 * 27 + e];
    __syncthreads();
    if (tid < cnt) {
        #pragma unroll
        for (int k = 0; k < 27; k++) {
            int v = s[tid * 27 + k];
            if ((unsigned)v >= (unsigned)N) v = -1;
            g_neighT[(size_t)k * ROW_CAP + n0 + tid] = v;
        }
    }
}

// ------------------------- weight prep (+ stats zero) -------------------------
// m16n8k16 B frag: lane l: reg0 = B[2q+{0,1}][g], reg1 = B[2q+8+{0,1}][g],
// q=l&3, g=l>>2. uint4 packs kstep0 (c0:16) and kstep1 (c16:32).
__global__ __launch_bounds__(256) void prep_weights_kernel(const float* __restrict__ weight) {
    int k = blockIdx.x;
    int t = threadIdx.x;
    if (k == 0 && t < 128) {
        if (t < 64) g_sum[t] = 0.0f; else g_sumsq[t - 64] = 0.0f;
    }
    int lane = t & 31;
    int nt = t >> 5;
    int q = lane & 3;
    int g = lane >> 2;
    int n = nt * 8 + g;
    const float* wk = weight + k * 2048;  // [32 c][64 o]

    uint4 v;
    v.x = pack_h2(wk[(2 * q) * 64 + n],      wk[(2 * q + 1) * 64 + n]);
    v.y = pack_h2(wk[(2 * q + 8) * 64 + n],  wk[(2 * q + 9) * 64 + n]);
    v.z = pack_h2(wk[(16 + 2 * q) * 64 + n], wk[(16 + 2 * q + 1) * 64 + n]);
    v.w = pack_h2(wk[(16 + 2 * q + 8) * 64 + n], wk[(16 + 2 * q + 9) * 64 + n]);
    g_Bfrag4[(k * 8 + nt) * 32 + lane] = v;
}

// ------------------------- conv kernel -------------------------
// block = 256 nodes x 64 outs, 256 threads, warps: warp_m = wid>>1, warp_n = wid&1.
// dynamic smem: A 4x16KB | B 4x4KB = 80KB.
__global__ __launch_bounds__(256) void conv_kernel(
    float* __restrict__ out,            // [N,64]
    int N)
{
    extern __shared__ __align__(256) uint8_t dyn[];
    const uint32_t aA = smem_u32(dyn);
    const uint32_t aB = aA + 4 * 16384;
    __shared__ float red_sum[8 * 32];
    __shared__ float red_sq[8 * 32];

    const int tid = threadIdx.x;
    const int wid = tid >> 5;
    const int lane = tid & 31;
    const int warp_m = wid >> 1;
    const int warp_n = wid & 1;
    const int n0 = blockIdx.x * 256;

    // A gather: thread t owns row t (4x16B chunks, chunk^((row>>1)&3) swizzle)
    const uint32_t gsw = ((uint32_t)(tid >> 1) & 3);
    const uint32_t adst = (uint32_t)tid * 64;
    const bool row_valid = (n0 + tid < N);

    // ldmatrix relative offsets within an m16 tile (ks = 0,1)
    uint32_t lm_rel[2];
    {
        uint32_t r = (uint32_t)(lane & 15);
        uint32_t rx = (r >> 1) & 3;
        #pragma unroll
        for (int ks = 0; ks < 2; ks++) {
            uint32_t chunk = (uint32_t)(ks * 2 + (lane >> 4));
            lm_rel[ks] = r * 64 + ((chunk ^ rx) << 4);
        }
    }
    const uint32_t atile = (uint32_t)(warp_m * 64) * 64;   // byte offset of warp's rows

    float acc[4][4][4];
    #pragma unroll
    for (int mt = 0; mt < 4; mt++)
        #pragma unroll
        for (int nt = 0; nt < 4; nt++)
            #pragma unroll
            for (int i = 0; i < 4; i++) acc[mt][nt][i] = 0.0f;

    auto issue_stage = [&](int k) {
        int s = k & 3;
        // B frags: 4KB, 1 chunk/thread
        cp_async16(aB + s * 4096 + tid * 16,
                   (const uint8_t*)g_Bfrag4 + (size_t)k * 4096 + tid * 16);
        // A: one row per thread
        int idx = row_valid ? g_neighT[(size_t)k * ROW_CAP + n0 + tid] : -1;
        const uint8_t* src = (idx >= 0) ? g_dataF16 + (size_t)idx * 64
                                        : (const uint8_t*)g_zero_row;
        uint32_t db = aA + s * 16384 + adst;
        #pragma unroll
        for (uint32_t j = 0; j < 4; j++)
            cp_async16(db + ((j ^ gsw) << 4), src + j * 16);
        CP_COMMIT();
    };

    issue_stage(0);
    issue_stage(1);
    issue_stage(2);

    for (int k = 0; k < 27; k++) {
        if (k + 3 < 27) issue_stage(k + 3);
        else CP_COMMIT();                  // empty group keeps wait count uniform
        CP_WAIT3();
        __syncthreads();

        const int s = k & 3;
        // B frags for this warp's n32 half: 4 LDS.128, reused across 4 m-tiles
        uint4 bv[4];
        {
            const uint4* bbuf = (const uint4*)(dyn + 4 * 16384 + s * 4096);
            const uint4* bp = bbuf + (warp_n * 4) * 32 + lane;
            #pragma unroll
            for (int nt = 0; nt < 4; nt++) bv[nt] = bp[nt * 32];
        }
        const uint32_t abase = aA + s * 16384 + atile;
        #pragma unroll
        for (int mt = 0; mt < 4; mt++) {
            uint32_t af0[4], af1[4];
            ldmatrix_x4(af0, abase + (uint32_t)(mt * 16 * 64) + lm_rel[0]);
            ldmatrix_x4(af1, abase + (uint32_t)(mt * 16 * 64) + lm_rel[1]);
            #pragma unroll
            for (int nt = 0; nt < 4; nt++) {
                mma_f16(acc[mt][nt], af0, bv[nt].x, bv[nt].y);
                mma_f16(acc[mt][nt], af1, bv[nt].z, bv[nt].w);
            }
        }
        __syncthreads();   // readers done before this stage is refilled
    }

    // ---- epilogue ----
    const int q = lane & 3;
    const int g = lane >> 2;
    const int colb = warp_n * 32 + 2 * q;

    #pragma unroll
    for (int mt = 0; mt < 4; mt++) {
        int row0 = n0 + warp_m * 64 + mt * 16 + g;
        int row1 = row0 + 8;
        if (row0 < N) {
            float* po = out + (size_t)row0 * 64 + colb;
            #pragma unroll
            for (int nt = 0; nt < 4; nt++)
                *(float2*)(po + nt * 8) = make_float2(acc[mt][nt][0], acc[mt][nt][1]);
        }
        if (row1 < N) {
            float* po = out + (size_t)row1 * 64 + colb;
            #pragma unroll
            for (int nt = 0; nt < 4; nt++)
                *(float2*)(po + nt * 8) = make_float2(acc[mt][nt][2], acc[mt][nt][3]);
        }
    }

    // BN partials (invalid rows contributed exact zeros)
    float ps[8], pq[8];
    #pragma unroll
    for (int nt = 0; nt < 4; nt++) {
        float s0 = 0.f, s1 = 0.f, q0 = 0.f, q1 = 0.f;
        #pragma unroll
        for (int mt = 0; mt < 4; mt++) {
            s0 += acc[mt][nt][0] + acc[mt][nt][2];
            s1 += acc[mt][nt][1] + acc[mt][nt][3];
            q0 += acc[mt][nt][0] * acc[mt][nt][0] + acc[mt][nt][2] * acc[mt][nt][2];
            q1 += acc[mt][nt][1] * acc[mt][nt][1] + acc[mt][nt][3] * acc[mt][nt][3];
        }
        ps[2 * nt] = s0; ps[2 * nt + 1] = s1;
        pq[2 * nt] = q0; pq[2 * nt + 1] = q1;
    }
    #pragma unroll
    for (int i = 0; i < 8; i++) {
        #pragma unroll
        for (int off = 4; off < 32; off <<= 1) {
            ps[i] += __shfl_xor_sync(0xffffffffu, ps[i], off);
            pq[i] += __shfl_xor_sync(0xffffffffu, pq[i], off);
        }
    }
    if (g == 0) {   // lanes 0..3 hold warp totals for its 32 channels
        #pragma unroll
        for (int nt = 0; nt < 4; nt++) {
            int c = nt * 8 + 2 * q;        // local channel in warp's half
            red_sum[wid * 32 + c]     = ps[2 * nt];
            red_sum[wid * 32 + c + 1] = ps[2 * nt + 1];
            red_sq[wid * 32 + c]      = pq[2 * nt];
            red_sq[wid * 32 + c + 1]  = pq[2 * nt + 1];
        }
    }
    __syncthreads();
    if (tid < 64) {
        int half = tid >> 5, lc = tid & 31;
        float t = 0.f;
        #pragma unroll
        for (int jm = 0; jm < 4; jm++) t += red_sum[(2 * jm + half) * 32 + lc];
        atomicAdd(&g_sum[tid], t);
    } else if (tid < 128) {
        int c = tid - 64;
        int half = c >> 5, lc = c & 31;
        float t = 0.f;
        #pragma unroll
        for (int jm = 0; jm < 4; jm++) t += red_sq[(2 * jm + half) * 32 + lc];
        atomicAdd(&g_sumsq[c], t);
    }
}

// ------------------------- BN tail -------------------------
__global__ void finalize_stats_kernel(const float* __restrict__ gamma,
                                      const float* __restrict__ beta,
                                      float invN)
{
    int c = threadIdx.x;
    if (c < 64) {
        float mean = g_sum[c] * invN;
        float var  = fmaxf(g_sumsq[c] * invN - mean * mean, 0.0f);
        float sc   = gamma[c] * rsqrtf(var + 1e-5f);
        g_scale[c] = sc;
        g_shift[c] = beta[c] - mean * sc;
    }
}

__global__ __launch_bounds__(256) void bn_relu_kernel(float* __restrict__ out, int total4) {
    int i = blockIdx.x * 256 + threadIdx.x;
    if (i < total4) {
        float4 x = ((const float4*)out)[i];
        int cq = i & 15;
        float4 sc = ((const float4*)g_scale)[cq];
        float4 sh = ((const float4*)g_shift)[cq];
        float4 y;
        y.x = fmaxf(fmaf(x.x, sc.x, sh.x), 0.0f);
        y.y = fmaxf(fmaf(x.y, sc.y, sh.y), 0.0f);
        y.z = fmaxf(fmaf(x.z, sc.z, sh.z), 0.0f);
        y.w = fmaxf(fmaf(x.w, sc.w, sh.w), 0.0f);
        ((float4*)out)[i] = y;
    }
}

// ------------------------- launch -------------------------
extern "C" void kernel_launch(void* const* d_in, const int* in_sizes, int n_in,
                              void* d_out, int out_size)
{
    const float* data   = (const float*)d_in[0];   // [N,32]
    const int*   neigh  = (const int*)d_in[1];     // [N,27] int32
    const float* weight = (const float*)d_in[2];   // [27,32,64]
    const float* gamma  = (const float*)d_in[3];
    const float* beta   = (const float*)d_in[4];
    float* out = (float*)d_out;

    int N = in_sizes[0] / 32;

    // One-time opt-in: 80KB dynamic smem exceeds the 48KB default.
    // Runs on the (uncaptured) correctness call; skipped during graph capture.
    static bool configured = false;
    if (!configured) {
        cudaFuncSetAttribute(conv_kernel,
                             cudaFuncAttributeMaxDynamicSharedMemorySize, 81920);
        configured = true;
    }

    int nb = (N + 255) / 256;
    prep_data_kernel<<<nb, 256>>>(data, N);
    prep_neigh_kernel<<<nb, 256>>>(neigh, N);
    prep_weights_kernel<<<27, 256>>>(weight);
    conv_kernel<<<nb, 256, 81920>>>(out, N);
    finalize_stats_kernel<<<1, 64>>>(gamma, beta, 1.0f / (float)N);
    int total4 = N * 16;
    bn_relu_kernel<<<(total4 + 255) / 256, 256>>>(out, total4);
}

// round 11
// speedup vs baseline: 1.1990x; 1.1990x over previous
#include <cuda_runtime.h>
#include <cuda_fp16.h>
#include <cstdint>

// OctreeConvBnRelu via warp-level mma.sync (HMMA fp16, f32 accum).
// Round 11: R9 skeleton (128-row block, 3-stage cp.async, 36KB dyn smem) with
// 4m x 2n warp grid (warp tile 32x32) to halve B-fragment LDS without R10's
// register explosion (acc stays 32 floats/thread). neigh pre-transposed.

#define DEVFN __device__ __forceinline__

DEVFN uint32_t smem_u32(const void* p) {
    uint32_t a;
    asm("{ .reg .u64 t; cvta.to.shared.u64 t, %1; cvt.u32.u64 %0, t; }" : "=r"(a) : "l"(p));
    return a;
}
DEVFN uint32_t pack_h2(float x, float y) {
    __half2 v = __halves2half2(__float2half_rn(x), __float2half_rn(y));  // x = low
    return *(uint32_t*)&v;
}
DEVFN void ldmatrix_x4(uint32_t* r, uint32_t addr) {
    asm volatile("ldmatrix.sync.aligned.m8n8.x4.shared.b16 {%0,%1,%2,%3}, [%4];"
                 : "=r"(r[0]), "=r"(r[1]), "=r"(r[2]), "=r"(r[3]) : "r"(addr));
}
DEVFN void mma_f16(float* d, const uint32_t* a, uint32_t b0, uint32_t b1) {
    asm volatile(
        "mma.sync.aligned.m16n8k16.row.col.f32.f16.f16.f32 "
        "{%0,%1,%2,%3}, {%4,%5,%6,%7}, {%8,%9}, {%0,%1,%2,%3};"
        : "+f"(d[0]), "+f"(d[1]), "+f"(d[2]), "+f"(d[3])
        : "r"(a[0]), "r"(a[1]), "r"(a[2]), "r"(a[3]), "r"(b0), "r"(b1));
}
DEVFN void cp_async16(uint32_t smem_dst, const void* gsrc) {
    asm volatile("cp.async.cg.shared.global [%0], [%1], 16;"
                 :: "r"(smem_dst), "l"(gsrc) : "memory");
}
#define CP_COMMIT() asm volatile("cp.async.commit_group;" ::: "memory")

// ------------------------- globals -------------------------
__device__ float g_sum[64];
__device__ float g_sumsq[64];
__device__ __align__(16) float g_scale[64];
__device__ __align__(16) float g_shift[64];
// B fragments: [27][ntile 8][lane 32] uint4 = {ks0.x, ks0.y, ks1.x, ks1.y} (4KB/k)
__device__ __align__(16) uint4 g_Bfrag4[27 * 256];
// fp16 data image: row = 32 half = 64B
static const int ROW_CAP = 301056;
__device__ __align__(16) uint8_t g_dataF16[(size_t)ROW_CAP * 64];
__device__ __align__(16) uint8_t g_zero_row[64];   // stays zero
// transposed neighbor table: [27][ROW_CAP]
__device__ int g_neighT[27 * ROW_CAP];

// ------------------------- data prep: f32 row -> fp16 row -------------------------
__global__ __launch_bounds__(256) void prep_data_kernel(const float* __restrict__ data, int N) {
    int r = blockIdx.x * 256 + threadIdx.x;
    if (r >= N || r >= ROW_CAP) return;
    const float4* src = (const float4*)(data + (size_t)r * 32);
    uint32_t u[16];
    #pragma unroll
    for (int i = 0; i < 8; i++) {
        float4 v = src[i];
        u[2 * i]     = pack_h2(v.x, v.y);
        u[2 * i + 1] = pack_h2(v.z, v.w);
    }
    uint4* dst = (uint4*)(g_dataF16 + (size_t)r * 64);
    #pragma unroll
    for (int i = 0; i < 4; i++)
        dst[i] = make_uint4(u[4 * i], u[4 * i + 1], u[4 * i + 2], u[4 * i + 3]);
}

// ------------------------- neigh transpose: [N,27] -> [27][N] -------------------------
__global__ __launch_bounds__(256) void prep_neigh_kernel(const int* __restrict__ neigh, int N) {
    __shared__ int s[256 * 27];
    int n0 = blockIdx.x * 256;
    int tid = threadIdx.x;
    int cnt = N - n0;
    if (cnt > 256) cnt = 256;
    for (int e = tid; e < cnt * 27; e += 256) s[e] = neigh[(size_t)n0 * 27 + e];
    __syncthreads();
    if (tid < cnt) {
        #pragma unroll
        for (int k = 0; k < 27; k++) {
            int v = s[tid * 27 + k];
            if ((unsigned)v >= (unsigned)N) v = -1;
            g_neighT[(size_t)k * ROW_CAP + n0 + tid] = v;
        }
    }
}

// ------------------------- weight prep (+ stats zero) -------------------------
// m16n8k16 B frag: lane l: reg0 = B[2q+{0,1}][g], reg1 = B[2q+8+{0,1}][g],
// q=l&3, g=l>>2. uint4 packs kstep0 (c0:16) and kstep1 (c16:32).
__global__ __launch_bounds__(256) void prep_weights_kernel(const float* __restrict__ weight) {
    int k = blockIdx.x;
    int t = threadIdx.x;
    if (k == 0 && t < 128) {
        if (t < 64) g_sum[t] = 0.0f; else g_sumsq[t - 64] = 0.0f;
    }
    int lane = t & 31;
    int nt = t >> 5;
    int q = lane & 3;
    int g = lane >> 2;
    int n = nt * 8 + g;
    const float* wk = weight + k * 2048;  // [32 c][64 o]

    uint4 v;
    v.x = pack_h2(wk[(2 * q) * 64 + n],      wk[(2 * q + 1) * 64 + n]);
    v.y = pack_h2(wk[(2 * q + 8) * 64 + n],  wk[(2 * q + 9) * 64 + n]);
    v.z = pack_h2(wk[(16 + 2 * q) * 64 + n], wk[(16 + 2 * q + 1) * 64 + n]);
    v.w = pack_h2(wk[(16 + 2 * q + 8) * 64 + n], wk[(16 + 2 * q + 9) * 64 + n]);
    g_Bfrag4[(k * 8 + nt) * 32 + lane] = v;
}

// ------------------------- conv kernel -------------------------
// block = 128 nodes x 64 outs, 256 threads.
// warps: warp_m = wid>>1 (rows warp_m*32, 2 m-tiles), warp_n = wid&1 (32 cols).
// dynamic smem: A 3x8KB + B 3x4KB = 36KB.
__global__ __launch_bounds__(256, 3) void conv_kernel(
    float* __restrict__ out,            // [N,64]
    int N)
{
    extern __shared__ __align__(256) uint8_t dyn[];
    const uint32_t aA = smem_u32(dyn);
    const uint32_t aB = aA + 3 * 8192;
    __shared__ float red_sum[8 * 32];
    __shared__ float red_sq[8 * 32];

    const int tid = threadIdx.x;
    const int wid = tid >> 5;
    const int lane = tid & 31;
    const int warp_m = wid >> 1;
    const int warp_n = wid & 1;
    const int n0 = blockIdx.x * 128;

    // A gather: thread t owns row t>>1, chunks j0 = (t&1)*2, j0+1 (32B of a row)
    const int grow = tid >> 1;
    const int j0 = (tid & 1) * 2;
    const uint32_t gsw = ((uint32_t)(grow >> 1) & 3);     // chunk xor for this row
    const uint32_t adst = (uint32_t)grow * 64;
    const bool row_valid = (n0 + grow < N);

    // ldmatrix relative offsets (ks = 0,1) for this warp's base row
    uint32_t lm_rel[2];
    {
        uint32_t r = (uint32_t)(warp_m * 32 + (lane & 15));
        uint32_t rx = (r >> 1) & 3;
        #pragma unroll
        for (int ks = 0; ks < 2; ks++) {
            uint32_t chunk = (uint32_t)(ks * 2 + (lane >> 4));
            lm_rel[ks] = r * 64 + ((chunk ^ rx) << 4);
        }
    }

    float acc[2][4][4];
    #pragma unroll
    for (int mt = 0; mt < 2; mt++)
        #pragma unroll
        for (int nt = 0; nt < 4; nt++)
            #pragma unroll
            for (int i = 0; i < 4; i++) acc[mt][nt][i] = 0.0f;

    auto issue_stage = [&](int k, int s) {
        // B frags: 4KB contiguous, 1 chunk/thread
        cp_async16(aB + s * 4096 + tid * 16,
                   (const uint8_t*)g_Bfrag4 + (size_t)k * 4096 + tid * 16);
        // A: half a row per thread
        int idx = row_valid ? g_neighT[(size_t)k * ROW_CAP + n0 + grow] : -1;
        const uint8_t* src = (idx >= 0) ? g_dataF16 + (size_t)idx * 64
                                        : (const uint8_t*)g_zero_row;
        uint32_t db = aA + s * 8192 + adst;
        cp_async16(db + (((uint32_t)j0 ^ gsw) << 4),       src + j0 * 16);
        cp_async16(db + ((((uint32_t)j0 + 1) ^ gsw) << 4), src + j0 * 16 + 16);
        CP_COMMIT();
    };

    issue_stage(0, 0);
    issue_stage(1, 1);

    int s = 0;                 // stage of current k
    int s2 = 2;                // stage to fill next
    for (int k = 0; k < 27; k++) {
        if (k < 25) {
            issue_stage(k + 2, s2);
            asm volatile("cp.async.wait_group 2;" ::: "memory");
        } else if (k == 25) {
            asm volatile("cp.async.wait_group 1;" ::: "memory");
        } else {
            asm volatile("cp.async.wait_group 0;" ::: "memory");
        }
        __syncthreads();

        // B frags for this warp's 32-col half: 4 LDS.128, reused across 2 m-tiles
        uint4 bv[4];
        {
            const uint4* bbuf = (const uint4*)(dyn + 3 * 8192 + s * 4096);
            const uint4* bp = bbuf + (warp_n * 4) * 32 + lane;
            #pragma unroll
            for (int nt = 0; nt < 4; nt++) bv[nt] = bp[nt * 32];
        }
        const uint32_t abase = aA + s * 8192;
        #pragma unroll
        for (int mt = 0; mt < 2; mt++) {
            uint32_t af0[4], af1[4];
            ldmatrix_x4(af0, abase + (uint32_t)(mt * 16 * 64) + lm_rel[0]);
            ldmatrix_x4(af1, abase + (uint32_t)(mt * 16 * 64) + lm_rel[1]);
            #pragma unroll
            for (int nt = 0; nt < 4; nt++) {
                mma_f16(acc[mt][nt], af0, bv[nt].x, bv[nt].y);
                mma_f16(acc[mt][nt], af1, bv[nt].z, bv[nt].w);
            }
        }
        __syncthreads();   // readers done before this stage is refilled

        s = (s == 2) ? 0 : s + 1;
        s2 = (s2 == 2) ? 0 : s2 + 1;
    }

    // ---- epilogue ----
    const int q = lane & 3;
    const int g = lane >> 2;
    const int colb = warp_n * 32 + 2 * q;

    #pragma unroll
    for (int mt = 0; mt < 2; mt++) {
        int row0 = n0 + warp_m * 32 + mt * 16 + g;
        int row1 = row0 + 8;
        if (row0 < N) {
            float* po = out + (size_t)row0 * 64 + colb;
            #pragma unroll
            for (int nt = 0; nt < 4; nt++)
                *(float2*)(po + nt * 8) = make_float2(acc[mt][nt][0], acc[mt][nt][1]);
        }
        if (row1 < N) {
            float* po = out + (size_t)row1 * 64 + colb;
            #pragma unroll
            for (int nt = 0; nt < 4; nt++)
                *(float2*)(po + nt * 8) = make_float2(acc[mt][nt][2], acc[mt][nt][3]);
        }
    }

    // BN partials (invalid rows contributed exact zeros)
    float ps[8], pq[8];
    #pragma unroll
    for (int nt = 0; nt < 4; nt++) {
        float s0 = 0.f, s1 = 0.f, q0 = 0.f, q1 = 0.f;
        #pragma unroll
        for (int mt = 0; mt < 2; mt++) {
            s0 += acc[mt][nt][0] + acc[mt][nt][2];
            s1 += acc[mt][nt][1] + acc[mt][nt][3];
            q0 += acc[mt][nt][0] * acc[mt][nt][0] + acc[mt][nt][2] * acc[mt][nt][2];
            q1 += acc[mt][nt][1] * acc[mt][nt][1] + acc[mt][nt][3] * acc[mt][nt][3];
        }
        ps[2 * nt] = s0; ps[2 * nt + 1] = s1;
        pq[2 * nt] = q0; pq[2 * nt + 1] = q1;
    }
    #pragma unroll
    for (int i = 0; i < 8; i++) {
        #pragma unroll
        for (int off = 4; off < 32; off <<= 1) {
            ps[i] += __shfl_xor_sync(0xffffffffu, ps[i], off);
            pq[i] += __shfl_xor_sync(0xffffffffu, pq[i], off);
        }
    }
    if (g == 0) {   // lanes 0..3 hold warp totals for its 32 channels
        #pragma unroll
        for (int nt = 0; nt < 4; nt++) {
            int c = nt * 8 + 2 * q;
            red_sum[wid * 32 + c]     = ps[2 * nt];
            red_sum[wid * 32 + c + 1] = ps[2 * nt + 1];
            red_sq[wid * 32 + c]      = pq[2 * nt];
            red_sq[wid * 32 + c + 1]  = pq[2 * nt + 1];
        }
    }
    __syncthreads();
    if (tid < 64) {
        int half = tid >> 5, lc = tid & 31;
        float t = 0.f;
        #pragma unroll
        for (int jm = 0; jm < 4; jm++) t += red_sum[(2 * jm + half) * 32 + lc];
        atomicAdd(&g_sum[tid], t);
    } else if (tid < 128) {
        int c = tid - 64;
        int half = c >> 5, lc = c & 31;
        float t = 0.f;
        #pragma unroll
        for (int jm = 0; jm < 4; jm++) t += red_sq[(2 * jm + half) * 32 + lc];
        atomicAdd(&g_sumsq[c], t);
    }
}

// ------------------------- BN tail -------------------------
__global__ void finalize_stats_kernel(const float* __restrict__ gamma,
                                      const float* __restrict__ beta,
                                      float invN)
{
    int c = threadIdx.x;
    if (c < 64) {
        float mean = g_sum[c] * invN;
        float var  = fmaxf(g_sumsq[c] * invN - mean * mean, 0.0f);
        float sc   = gamma[c] * rsqrtf(var + 1e-5f);
        g_scale[c] = sc;
        g_shift[c] = beta[c] - mean * sc;
    }
}

__global__ __launch_bounds__(256) void bn_relu_kernel(float* __restrict__ out, int total4) {
    int i = blockIdx.x * 256 + threadIdx.x;
    if (i < total4) {
        float4 x = ((const float4*)out)[i];
        int cq = i & 15;
        float4 sc = ((const float4*)g_scale)[cq];
        float4 sh = ((const float4*)g_shift)[cq];
        float4 y;
        y.x = fmaxf(fmaf(x.x, sc.x, sh.x), 0.0f);
        y.y = fmaxf(fmaf(x.y, sc.y, sh.y), 0.0f);
        y.z = fmaxf(fmaf(x.z, sc.z, sh.z), 0.0f);
        y.w = fmaxf(fmaf(x.w, sc.w, sh.w), 0.0f);
        ((float4*)out)[i] = y;
    }
}

// ------------------------- launch -------------------------
extern "C" void kernel_launch(void* const* d_in, const int* in_sizes, int n_in,
                              void* d_out, int out_size)
{
    const float* data   = (const float*)d_in[0];   // [N,32]
    const int*   neigh  = (const int*)d_in[1];     // [N,27] int32
    const float* weight = (const float*)d_in[2];   // [27,32,64]
    const float* gamma  = (const float*)d_in[3];
    const float* beta   = (const float*)d_in[4];
    float* out = (float*)d_out;

    int N = in_sizes[0] / 32;

    int nb256 = (N + 255) / 256;
    prep_data_kernel<<<nb256, 256>>>(data, N);
    prep_neigh_kernel<<<nb256, 256>>>(neigh, N);
    prep_weights_kernel<<<27, 256>>>(weight);
    conv_kernel<<<(N + 127) / 128, 256, 36864>>>(out, N);
    finalize_stats_kernel<<<1, 64>>>(gamma, beta, 1.0f / (float)N);
    int total4 = N * 16;
    bn_relu_kernel<<<(total4 + 255) / 256, 256>>>(out, total4);
}